// round 4
// baseline (speedup 1.0000x reference)
#include <cuda_runtime.h>

typedef unsigned long long u64;

#define THREADS 384
#define PTS_PER_CTA 192     // 384 threads, 2 lanes per point
#define NP 50000
#define HID 128

// ---- shared-memory layout (in floats) ----
#define SM_W2H 0            // 128*128
#define SM_W2G 16384        // 128*128
#define SM_W1H 32768        // 128*4
#define SM_W1G 33280        // 128*4
#define SM_B1H 33792        // 128
#define SM_B1G 33920        // 128
#define SM_B2H 34048        // 128
#define SM_B2G 34176        // 128
#define SM_OW  34304        // 3*128
#define SM_OB  34688        // 3
#define SM_FLOATS 34692
#define SM_BYTES (SM_FLOATS * 4)

__device__ __forceinline__ u64 ffma2(u64 a, u64 b, u64 c) {
    u64 d;
    asm("fma.rn.f32x2 %0, %1, %2, %3;" : "=l"(d) : "l"(a), "l"(b), "l"(c));
    return d;
}
__device__ __forceinline__ u64 pack2(float lo, float hi) {
    u64 r;
    asm("mov.b64 %0, {%1, %2};" : "=l"(r) : "f"(lo), "f"(hi));
    return r;
}
__device__ __forceinline__ float red2(u64 v) {
    float lo, hi;
    asm("mov.b64 {%0, %1}, %2;" : "=f"(lo), "=f"(hi) : "l"(v));
    return lo + hi;
}
__device__ __forceinline__ float sigmoid_f(float x) {
    return __fdividef(1.0f, 1.0f + __expf(-x));
}

__global__ void __launch_bounds__(THREADS, 1)
node_rk4_kernel(const float* __restrict__ x0,
                const float* __restrict__ h1w, const float* __restrict__ h1b,
                const float* __restrict__ g1w, const float* __restrict__ g1b,
                const float* __restrict__ h2w, const float* __restrict__ h2b,
                const float* __restrict__ g2w, const float* __restrict__ g2b,
                const float* __restrict__ ow,  const float* __restrict__ ob,
                float* __restrict__ out, int B, int N)
{
    extern __shared__ float sm[];
    const int tid = threadIdx.x;

    // ---- cooperative weight staging ----
    for (int i = tid; i < HID * HID; i += THREADS) {
        sm[SM_W2H + i] = h2w[i];
        sm[SM_W2G + i] = g2w[i];
    }
    for (int i = tid; i < HID * 4; i += THREADS) {
        sm[SM_W1H + i] = h1w[i];
        sm[SM_W1G + i] = g1w[i];
    }
    for (int i = tid; i < HID; i += THREADS) {
        sm[SM_B1H + i] = h1b[i];
        sm[SM_B1G + i] = g1b[i];
        sm[SM_B2H + i] = h2b[i];
        sm[SM_B2G + i] = g2b[i];
    }
    for (int i = tid; i < 3 * HID; i += THREADS) sm[SM_OW + i] = ow[i];
    if (tid < 3) sm[SM_OB + tid] = ob[tid];
    __syncthreads();

    const int P = B * N;
    const int e = tid & 1;            // which K-half of the point this lane owns
    const int q = tid >> 1;           // point index within CTA
    int p = blockIdx.x * PTS_PER_CTA + q;
    const bool valid = (p < P);
    if (!valid) p = P - 1;            // clamp: keep all lanes active for shfl
    const int b = p / N;
    const int n = p - b * N;

    const float* xb = x0 + (size_t)b * 3 * N + n;
    const float x0r0 = xb[0];
    const float x0r1 = xb[N];
    const float x0r2 = xb[2 * N];

    const float4* w1h4 = (const float4*)(sm + SM_W1H);
    const float4* w1g4 = (const float4*)(sm + SM_W1G);
    const int c0 = e * 64;            // this lane's channel range [c0, c0+64)

    float k10 = 0.f, k11 = 0.f, k12 = 0.f;
    float k20 = 0.f, k21 = 0.f, k22 = 0.f;
    float k30 = 0.f, k31 = 0.f, k32 = 0.f;
    float r0 = 0.f, r1 = 0.f, r2 = 0.f;

    const float third = 1.0f / 3.0f;

    #pragma unroll 1
    for (int s = 0; s < 4; ++s) {
        float xin0, xin1, xin2, tt;
        if (s == 0) {
            xin0 = x0r0; xin1 = x0r1; xin2 = x0r2; tt = 0.0f;
        } else if (s == 1) {
            xin0 = fmaf(k10, third, x0r0);
            xin1 = fmaf(k11, third, x0r1);
            xin2 = fmaf(k12, third, x0r2);
            tt = third;
        } else if (s == 2) {
            xin0 = x0r0 + k20 - k10 * third;
            xin1 = x0r1 + k21 - k11 * third;
            xin2 = x0r2 + k22 - k12 * third;
            tt = third * 2.0f;
        } else {
            xin0 = x0r0 + k10 - k20 + k30;
            xin1 = x0r1 + k11 - k21 + k31;
            xin2 = x0r2 + k12 - k22 + k32;
            tt = 1.0f;
        }

        // ---- layer 1: this lane's 64 channels, packed in 32 f32x2 regs ----
        u64 z1[32];
        #pragma unroll 8
        for (int j = 0; j < 32; ++j) {
            const int c = c0 + 2 * j;
            float4 whA = w1h4[c], whB = w1h4[c + 1];
            float4 wgA = w1g4[c], wgB = w1g4[c + 1];
            float hA = fmaf(whA.x, xin0, fmaf(whA.y, xin1,
                       fmaf(whA.z, xin2, fmaf(whA.w, tt, sm[SM_B1H + c]))));
            float hB = fmaf(whB.x, xin0, fmaf(whB.y, xin1,
                       fmaf(whB.z, xin2, fmaf(whB.w, tt, sm[SM_B1H + c + 1]))));
            float gA = fmaf(wgA.x, xin0, fmaf(wgA.y, xin1,
                       fmaf(wgA.z, xin2, fmaf(wgA.w, tt, sm[SM_B1G + c]))));
            float gB = fmaf(wgB.x, xin0, fmaf(wgB.y, xin1,
                       fmaf(wgB.z, xin2, fmaf(wgB.w, tt, sm[SM_B1G + c + 1]))));
            float zA = fmaxf(hA * sigmoid_f(gA), 0.0f);
            float zB = fmaxf(hB * sigmoid_f(gB), 0.0f);
            z1[j] = pack2(zA, zB);
        }

        // ---- layer 2 (each lane does its K-half) fused with output proj ----
        float o0 = 0.f, o1 = 0.f, o2 = 0.f;
        #pragma unroll 1
        for (int o = 0; o < HID; o += 2) {
            const ulonglong2* rh  = (const ulonglong2*)(sm + SM_W2H + o * HID + c0);
            const ulonglong2* rg  = (const ulonglong2*)(sm + SM_W2G + o * HID + c0);
            const ulonglong2* rh1 = rh + 32;   // next row: +128 floats
            const ulonglong2* rg1 = rg + 32;
            u64 ah0 = 0ull, ah1 = 0ull, ag0 = 0ull, ag1 = 0ull;
            #pragma unroll 4
            for (int ii = 0; ii < 16; ++ii) {
                ulonglong2 wh0 = rh[ii];
                ulonglong2 wh1 = rh1[ii];
                ulonglong2 wg0 = rg[ii];
                ulonglong2 wg1 = rg1[ii];
                u64 za = z1[2 * ii];
                u64 zb = z1[2 * ii + 1];
                ah0 = ffma2(wh0.x, za, ah0); ah0 = ffma2(wh0.y, zb, ah0);
                ah1 = ffma2(wh1.x, za, ah1); ah1 = ffma2(wh1.y, zb, ah1);
                ag0 = ffma2(wg0.x, za, ag0); ag0 = ffma2(wg0.y, zb, ag0);
                ag1 = ffma2(wg1.x, za, ag1); ag1 = ffma2(wg1.y, zb, ag1);
            }
            // combine halves across the lane pair
            float h0 = red2(ah0); h0 += __shfl_xor_sync(0xffffffffu, h0, 1);
            float g0 = red2(ag0); g0 += __shfl_xor_sync(0xffffffffu, g0, 1);
            float h1 = red2(ah1); h1 += __shfl_xor_sync(0xffffffffu, h1, 1);
            float g1 = red2(ag1); g1 += __shfl_xor_sync(0xffffffffu, g1, 1);
            h0 += sm[SM_B2H + o];     g0 += sm[SM_B2G + o];
            h1 += sm[SM_B2H + o + 1]; g1 += sm[SM_B2G + o + 1];
            float z20 = fmaxf(h0 * sigmoid_f(g0), 0.0f);
            float z21 = fmaxf(h1 * sigmoid_f(g1), 0.0f);
            o0 = fmaf(sm[SM_OW + o],             z20, o0);
            o0 = fmaf(sm[SM_OW + o + 1],         z21, o0);
            o1 = fmaf(sm[SM_OW + HID + o],       z20, o1);
            o1 = fmaf(sm[SM_OW + HID + o + 1],   z21, o1);
            o2 = fmaf(sm[SM_OW + 2*HID + o],     z20, o2);
            o2 = fmaf(sm[SM_OW + 2*HID + o + 1], z21, o2);
        }

        float v0 = tanhf(o0 + sm[SM_OB + 0]) * 0.5f;
        float v1 = tanhf(o1 + sm[SM_OB + 1]) * 0.5f;
        float v2 = tanhf(o2 + sm[SM_OB + 2]) * 0.5f;

        if (s == 0)      { k10 = v0; k11 = v1; k12 = v2; }
        else if (s == 1) { k20 = v0; k21 = v1; k22 = v2; }
        else if (s == 2) { k30 = v0; k31 = v1; k32 = v2; }
        else {
            r0 = x0r0 + 0.125f * (k10 + 3.0f * (k20 + k30) + v0);
            r1 = x0r1 + 0.125f * (k11 + 3.0f * (k21 + k31) + v1);
            r2 = x0r2 + 0.125f * (k12 + 3.0f * (k22 + k32) + v2);
        }
    }

    if (valid && e == 0) {
        float* op = out + (size_t)b * 3 * N + n;
        op[0]     = r0;
        op[N]     = r1;
        op[2 * N] = r2;
    }
}

extern "C" void kernel_launch(void* const* d_in, const int* in_sizes, int n_in,
                              void* d_out, int out_size)
{
    const float* x0  = (const float*)d_in[0];
    const float* h1w = (const float*)d_in[1];
    const float* h1b = (const float*)d_in[2];
    const float* g1w = (const float*)d_in[3];
    const float* g1b = (const float*)d_in[4];
    const float* h2w = (const float*)d_in[5];
    const float* h2b = (const float*)d_in[6];
    const float* g2w = (const float*)d_in[7];
    const float* g2b = (const float*)d_in[8];
    const float* ow  = (const float*)d_in[9];
    const float* ob  = (const float*)d_in[10];
    float* out = (float*)d_out;

    const int N = NP;
    const int B = in_sizes[0] / (3 * N);
    const int P = B * N;

    cudaFuncSetAttribute(node_rk4_kernel,
                         cudaFuncAttributeMaxDynamicSharedMemorySize, SM_BYTES);

    const int blocks = (P + PTS_PER_CTA - 1) / PTS_PER_CTA;
    node_rk4_kernel<<<blocks, THREADS, SM_BYTES>>>(
        x0, h1w, h1b, g1w, g1b, h2w, h2b, g2w, g2b, ow, ob, out, B, N);
}

// round 6
// speedup vs baseline: 1.5782x; 1.5782x over previous
#include <cuda_runtime.h>

typedef unsigned long long u64;

#define THREADS 512
#define TILE_P 128          // points per CTA
#define NP 50000
#define HID 128

// ---- shared memory layout (float offsets) ----
#define SM_W2HT 0                 // [k][out] 128*128
#define SM_W2GT 16384             // [k][out] 128*128
#define SM_Z    32768             // z1: [k][pt] stride 128 ; z2t: [pt][out] stride 132
#define SM_Z_SZ 16896
#define SM_W1H  (SM_Z + SM_Z_SZ)          // 128*4
#define SM_W1G  (SM_W1H + 512)            // 128*4
#define SM_B1H  (SM_W1G + 512)            // 128
#define SM_B1G  (SM_B1H + 128)
#define SM_B2H  (SM_B1G + 128)
#define SM_B2G  (SM_B2H + 128)
#define SM_OW   (SM_B2G + 128)            // 3*128
#define SM_OB   (SM_OW + 384)             // 4 (3 used)
#define SM_X0   (SM_OB + 4)               // 3*128
#define SM_K1   (SM_X0 + 384)
#define SM_K2   (SM_K1 + 384)
#define SM_K3   (SM_K2 + 384)
#define SM_XIN  (SM_K3 + 384)             // 3*128
#define SM_FLOATS (SM_XIN + 384)
#define SM_BYTES  (SM_FLOATS * 4)

#define Z2STR 132                  // z2t row stride (pad to break bank conflicts)

__device__ __forceinline__ u64 ffma2(u64 a, u64 b, u64 c) {
    u64 d;
    asm("fma.rn.f32x2 %0, %1, %2, %3;" : "=l"(d) : "l"(a), "l"(b), "l"(c));
    return d;
}
__device__ __forceinline__ u64 pack2(float lo, float hi) {
    u64 r;
    asm("mov.b64 %0, {%1, %2};" : "=l"(r) : "f"(lo), "f"(hi));
    return r;
}
__device__ __forceinline__ void unpack2(u64 v, float& lo, float& hi) {
    asm("mov.b64 {%0, %1}, %2;" : "=f"(lo), "=f"(hi) : "l"(v));
}
__device__ __forceinline__ float sigmoid_f(float x) {
    return __fdividef(1.0f, 1.0f + __expf(-x));
}

__global__ void __launch_bounds__(THREADS, 1)
node_rk4_kernel(const float* __restrict__ x0,
                const float* __restrict__ h1w, const float* __restrict__ h1b,
                const float* __restrict__ g1w, const float* __restrict__ g1b,
                const float* __restrict__ h2w, const float* __restrict__ h2b,
                const float* __restrict__ g2w, const float* __restrict__ g2b,
                const float* __restrict__ ow,  const float* __restrict__ ob,
                float* __restrict__ out, int B, int N)
{
    extern __shared__ float sm[];
    const int tid = threadIdx.x;
    const int P = B * N;

    // ---- staging: transpose layer-2 weights into [k][out] ----
    #pragma unroll 4
    for (int i = tid; i < HID * HID; i += THREADS) {
        const int o = i >> 7, k = i & 127;
        sm[SM_W2HT + k * HID + o] = h2w[i];
        sm[SM_W2GT + k * HID + o] = g2w[i];
    }
    for (int i = tid; i < HID * 4; i += THREADS) {
        sm[SM_W1H + i] = h1w[i];
        sm[SM_W1G + i] = g1w[i];
    }
    if (tid < HID) {
        sm[SM_B1H + tid] = h1b[tid];
        sm[SM_B1G + tid] = g1b[tid];
        sm[SM_B2H + tid] = h2b[tid];
        sm[SM_B2G + tid] = g2b[tid];
    }
    for (int i = tid; i < 3 * HID; i += THREADS) sm[SM_OW + i] = ow[i];
    if (tid < 3) sm[SM_OB + tid] = ob[tid];

    // ---- stage x0 for this CTA's 128 points ----
    if (tid < TILE_P) {
        int p = blockIdx.x * TILE_P + tid;
        if (p >= P) p = P - 1;
        const int b = p / N;
        const int n = p - b * N;
        const float* xb = x0 + (size_t)b * 3 * N + n;
        sm[SM_X0 + tid]       = xb[0];
        sm[SM_X0 + 128 + tid] = xb[N];
        sm[SM_X0 + 256 + tid] = xb[2 * N];
    }
    __syncthreads();

    const int og = tid & 31;          // out group: outs 4*og .. 4*og+3
    const int pg = tid >> 5;          // pt group (== warp id): pts 8*pg .. 8*pg+7

    const float third = 1.0f / 3.0f;
    const float tts[4] = {0.0f, third, 2.0f * third, 1.0f};

    #pragma unroll 1
    for (int s = 0; s < 4; ++s) {
        // ---- (a) per-point RK stage input ----
        if (tid < TILE_P) {
            const int j = tid;
            #pragma unroll
            for (int c = 0; c < 3; ++c) {
                const float xv = sm[SM_X0 + c * 128 + j];
                float xin;
                if (s == 0)      xin = xv;
                else if (s == 1) xin = fmaf(sm[SM_K1 + c * 128 + j], third, xv);
                else if (s == 2) xin = xv + sm[SM_K2 + c * 128 + j]
                                        - sm[SM_K1 + c * 128 + j] * third;
                else             xin = xv + sm[SM_K1 + c * 128 + j]
                                        - sm[SM_K2 + c * 128 + j]
                                        + sm[SM_K3 + c * 128 + j];
                sm[SM_XIN + c * 128 + j] = xin;
            }
        }
        __syncthreads();

        // ---- (b) layer 1: z1[k][p] for all 128x128 elements ----
        const float tt = tts[s];
        const float4* w1h4 = (const float4*)(sm + SM_W1H);
        const float4* w1g4 = (const float4*)(sm + SM_W1G);
        #pragma unroll 4
        for (int it = 0; it < (HID * TILE_P) / THREADS; ++it) {
            const int i = tid + it * THREADS;
            const int k = i >> 7, p = i & 127;
            const float xi0 = sm[SM_XIN + p];
            const float xi1 = sm[SM_XIN + 128 + p];
            const float xi2 = sm[SM_XIN + 256 + p];
            const float4 wh = w1h4[k];
            const float4 wg = w1g4[k];
            float h = fmaf(wh.x, xi0, fmaf(wh.y, xi1,
                      fmaf(wh.z, xi2, fmaf(wh.w, tt, sm[SM_B1H + k]))));
            float g = fmaf(wg.x, xi0, fmaf(wg.y, xi1,
                      fmaf(wg.z, xi2, fmaf(wg.w, tt, sm[SM_B1G + k]))));
            sm[SM_Z + k * 128 + p] = fmaxf(h * sigmoid_f(g), 0.0f);
        }
        __syncthreads();

        // ---- (c) layer-2 GEMM: 4 outs x 8 pts x {h,g} per thread ----
        u64 acch[16], accg[16];
        #pragma unroll
        for (int i = 0; i < 16; ++i) { acch[i] = 0ull; accg[i] = 0ull; }

        const float4* whp = (const float4*)(sm + SM_W2HT) + og;      // +32/iter
        const float4* wgp = (const float4*)(sm + SM_W2GT) + og;
        const ulonglong2* zq = (const ulonglong2*)(sm + SM_Z) + pg * 2; // +32/iter

        #pragma unroll 2
        for (int k = 0; k < HID; ++k) {
            const float4 wh = whp[k * 32];
            const float4 wg = wgp[k * 32];
            const ulonglong2 za = zq[k * 32];
            const ulonglong2 zb = zq[k * 32 + 1];
            u64 w;
            w = pack2(wh.x, wh.x);
            acch[0]  = ffma2(w, za.x, acch[0]);  acch[1]  = ffma2(w, za.y, acch[1]);
            acch[2]  = ffma2(w, zb.x, acch[2]);  acch[3]  = ffma2(w, zb.y, acch[3]);
            w = pack2(wh.y, wh.y);
            acch[4]  = ffma2(w, za.x, acch[4]);  acch[5]  = ffma2(w, za.y, acch[5]);
            acch[6]  = ffma2(w, zb.x, acch[6]);  acch[7]  = ffma2(w, zb.y, acch[7]);
            w = pack2(wh.z, wh.z);
            acch[8]  = ffma2(w, za.x, acch[8]);  acch[9]  = ffma2(w, za.y, acch[9]);
            acch[10] = ffma2(w, zb.x, acch[10]); acch[11] = ffma2(w, zb.y, acch[11]);
            w = pack2(wh.w, wh.w);
            acch[12] = ffma2(w, za.x, acch[12]); acch[13] = ffma2(w, za.y, acch[13]);
            acch[14] = ffma2(w, zb.x, acch[14]); acch[15] = ffma2(w, zb.y, acch[15]);
            w = pack2(wg.x, wg.x);
            accg[0]  = ffma2(w, za.x, accg[0]);  accg[1]  = ffma2(w, za.y, accg[1]);
            accg[2]  = ffma2(w, zb.x, accg[2]);  accg[3]  = ffma2(w, zb.y, accg[3]);
            w = pack2(wg.y, wg.y);
            accg[4]  = ffma2(w, za.x, accg[4]);  accg[5]  = ffma2(w, za.y, accg[5]);
            accg[6]  = ffma2(w, zb.x, accg[6]);  accg[7]  = ffma2(w, zb.y, accg[7]);
            w = pack2(wg.z, wg.z);
            accg[8]  = ffma2(w, za.x, accg[8]);  accg[9]  = ffma2(w, za.y, accg[9]);
            accg[10] = ffma2(w, zb.x, accg[10]); accg[11] = ffma2(w, zb.y, accg[11]);
            w = pack2(wg.w, wg.w);
            accg[12] = ffma2(w, za.x, accg[12]); accg[13] = ffma2(w, za.y, accg[13]);
            accg[14] = ffma2(w, zb.x, accg[14]); accg[15] = ffma2(w, zb.y, accg[15]);
        }
        __syncthreads();   // all z1 reads done; zbuf can be reused for z2t

        // ---- (d) gating epilogue -> z2t[pt][out] (stride Z2STR) ----
        {
            float z2r[4][8];     // [oo][pt in group]
            #pragma unroll
            for (int oo = 0; oo < 4; ++oo) {
                const int o = 4 * og + oo;
                const float bh = sm[SM_B2H + o];
                const float bg = sm[SM_B2G + o];
                #pragma unroll
                for (int pp = 0; pp < 4; ++pp) {
                    float h0, h1, g0, g1;
                    unpack2(acch[oo * 4 + pp], h0, h1);
                    unpack2(accg[oo * 4 + pp], g0, g1);
                    h0 += bh; h1 += bh; g0 += bg; g1 += bg;
                    z2r[oo][2 * pp]     = fmaxf(h0 * sigmoid_f(g0), 0.0f);
                    z2r[oo][2 * pp + 1] = fmaxf(h1 * sigmoid_f(g1), 0.0f);
                }
            }
            #pragma unroll
            for (int pp = 0; pp < 8; ++pp) {
                const int p = pg * 8 + pp;
                float4 v = make_float4(z2r[0][pp], z2r[1][pp], z2r[2][pp], z2r[3][pp]);
                *(float4*)(sm + SM_Z + p * Z2STR + 4 * og) = v;
            }
        }
        __syncthreads();

        // ---- (e) output projection + tanh + RK state update ----
        {
            const int pt   = tid >> 2;      // 0..127
            const int part = tid & 3;       // quarter of the 128 hidden outs
            const float4* zr = (const float4*)(sm + SM_Z + pt * Z2STR + part * 32);
            const float4* w0 = (const float4*)(sm + SM_OW + part * 32);
            const float4* w1 = (const float4*)(sm + SM_OW + 128 + part * 32);
            const float4* w2 = (const float4*)(sm + SM_OW + 256 + part * 32);
            float o0 = 0.f, o1 = 0.f, o2 = 0.f;
            #pragma unroll
            for (int i = 0; i < 8; ++i) {
                const float4 z4 = zr[i];
                const float4 a = w0[i], b4 = w1[i], c4 = w2[i];
                o0 = fmaf(a.x, z4.x, fmaf(a.y, z4.y, fmaf(a.z, z4.z, fmaf(a.w, z4.w, o0))));
                o1 = fmaf(b4.x, z4.x, fmaf(b4.y, z4.y, fmaf(b4.z, z4.z, fmaf(b4.w, z4.w, o1))));
                o2 = fmaf(c4.x, z4.x, fmaf(c4.y, z4.y, fmaf(c4.z, z4.z, fmaf(c4.w, z4.w, o2))));
            }
            o0 += __shfl_xor_sync(0xffffffffu, o0, 1);
            o0 += __shfl_xor_sync(0xffffffffu, o0, 2);
            o1 += __shfl_xor_sync(0xffffffffu, o1, 1);
            o1 += __shfl_xor_sync(0xffffffffu, o1, 2);
            o2 += __shfl_xor_sync(0xffffffffu, o2, 1);
            o2 += __shfl_xor_sync(0xffffffffu, o2, 2);

            if (part == 0) {
                const float v0 = tanhf(o0 + sm[SM_OB + 0]) * 0.5f;
                const float v1 = tanhf(o1 + sm[SM_OB + 1]) * 0.5f;
                const float v2 = tanhf(o2 + sm[SM_OB + 2]) * 0.5f;
                if (s == 0) {
                    sm[SM_K1 + pt] = v0; sm[SM_K1 + 128 + pt] = v1; sm[SM_K1 + 256 + pt] = v2;
                } else if (s == 1) {
                    sm[SM_K2 + pt] = v0; sm[SM_K2 + 128 + pt] = v1; sm[SM_K2 + 256 + pt] = v2;
                } else if (s == 2) {
                    sm[SM_K3 + pt] = v0; sm[SM_K3 + 128 + pt] = v1; sm[SM_K3 + 256 + pt] = v2;
                } else {
                    const int p = blockIdx.x * TILE_P + pt;
                    if (p < P) {
                        const int b = p / N;
                        const int n = p - b * N;
                        float* op = out + (size_t)b * 3 * N + n;
                        const float k4[3] = {v0, v1, v2};
                        #pragma unroll
                        for (int c = 0; c < 3; ++c) {
                            const float r = sm[SM_X0 + c * 128 + pt] + 0.125f *
                                (sm[SM_K1 + c * 128 + pt]
                                 + 3.0f * (sm[SM_K2 + c * 128 + pt] + sm[SM_K3 + c * 128 + pt])
                                 + k4[c]);
                            op[(size_t)c * N] = r;
                        }
                    }
                }
            }
        }
        __syncthreads();
    }
}

extern "C" void kernel_launch(void* const* d_in, const int* in_sizes, int n_in,
                              void* d_out, int out_size)
{
    const float* x0  = (const float*)d_in[0];
    const float* h1w = (const float*)d_in[1];
    const float* h1b = (const float*)d_in[2];
    const float* g1w = (const float*)d_in[3];
    const float* g1b = (const float*)d_in[4];
    const float* h2w = (const float*)d_in[5];
    const float* h2b = (const float*)d_in[6];
    const float* g2w = (const float*)d_in[7];
    const float* g2b = (const float*)d_in[8];
    const float* ow  = (const float*)d_in[9];
    const float* ob  = (const float*)d_in[10];
    float* out = (float*)d_out;

    const int N = NP;
    const int B = in_sizes[0] / (3 * N);
    const int P = B * N;

    cudaFuncSetAttribute(node_rk4_kernel,
                         cudaFuncAttributeMaxDynamicSharedMemorySize, SM_BYTES);

    const int blocks = (P + TILE_P - 1) / TILE_P;
    node_rk4_kernel<<<blocks, THREADS, SM_BYTES>>>(
        x0, h1w, h1b, g1w, g1b, h2w, h2b, g2w, g2b, ow, ob, out, B, N);
}

// round 7
// speedup vs baseline: 2.8654x; 1.8157x over previous
#include <cuda_runtime.h>

typedef unsigned long long u64;

#define THREADS 256
#define TILE_P 128          // points per CTA
#define PTS_T 16            // points per thread
#define NP 50000
#define HID 128

// ---- shared memory layout (float offsets) ----
#define SM_W2HT 0                 // [k][out] 128*128
#define SM_W2GT 16384             // [k][out] 128*128
#define SM_Z    32768             // z1: [k][pt] stride 128 ; z2t: [pt][out] stride 132
#define SM_Z_SZ 16896
#define SM_W1H  (SM_Z + SM_Z_SZ)          // 128*4
#define SM_W1G  (SM_W1H + 512)            // 128*4
#define SM_B1H  (SM_W1G + 512)            // 128
#define SM_B1G  (SM_B1H + 128)
#define SM_B2H  (SM_B1G + 128)
#define SM_B2G  (SM_B2H + 128)
#define SM_OW   (SM_B2G + 128)            // 3*128
#define SM_OB   (SM_OW + 384)             // 4 (3 used)
#define SM_X0   (SM_OB + 4)               // 3*128
#define SM_K1   (SM_X0 + 384)
#define SM_K2   (SM_K1 + 384)
#define SM_K3   (SM_K2 + 384)
#define SM_XIN  (SM_K3 + 384)             // 3*128
#define SM_FLOATS (SM_XIN + 384)
#define SM_BYTES  (SM_FLOATS * 4)

#define Z2STR 132                  // z2t row stride (pad to break bank conflicts)

__device__ __forceinline__ u64 ffma2(u64 a, u64 b, u64 c) {
    u64 d;
    asm("fma.rn.f32x2 %0, %1, %2, %3;" : "=l"(d) : "l"(a), "l"(b), "l"(c));
    return d;
}
__device__ __forceinline__ u64 pack2(float lo, float hi) {
    u64 r;
    asm("mov.b64 %0, {%1, %2};" : "=l"(r) : "f"(lo), "f"(hi));
    return r;
}
__device__ __forceinline__ void unpack2(u64 v, float& lo, float& hi) {
    asm("mov.b64 {%0, %1}, %2;" : "=f"(lo), "=f"(hi) : "l"(v));
}
__device__ __forceinline__ float sigmoid_f(float x) {
    return __fdividef(1.0f, 1.0f + __expf(-x));
}

__global__ void __launch_bounds__(THREADS, 1)
node_rk4_kernel(const float* __restrict__ x0,
                const float* __restrict__ h1w, const float* __restrict__ h1b,
                const float* __restrict__ g1w, const float* __restrict__ g1b,
                const float* __restrict__ h2w, const float* __restrict__ h2b,
                const float* __restrict__ g2w, const float* __restrict__ g2b,
                const float* __restrict__ ow,  const float* __restrict__ ob,
                float* __restrict__ out, int B, int N)
{
    extern __shared__ float sm[];
    const int tid = threadIdx.x;
    const int P = B * N;

    // ---- staging: transpose layer-2 weights into [k][out] ----
    #pragma unroll 4
    for (int i = tid; i < HID * HID; i += THREADS) {
        const int o = i >> 7, k = i & 127;
        sm[SM_W2HT + k * HID + o] = h2w[i];
        sm[SM_W2GT + k * HID + o] = g2w[i];
    }
    for (int i = tid; i < HID * 4; i += THREADS) {
        sm[SM_W1H + i] = h1w[i];
        sm[SM_W1G + i] = g1w[i];
    }
    if (tid < HID) {
        sm[SM_B1H + tid] = h1b[tid];
        sm[SM_B1G + tid] = g1b[tid];
        sm[SM_B2H + tid] = h2b[tid];
        sm[SM_B2G + tid] = g2b[tid];
    }
    for (int i = tid; i < 3 * HID; i += THREADS) sm[SM_OW + i] = ow[i];
    if (tid < 3) sm[SM_OB + tid] = ob[tid];

    // ---- stage x0 for this CTA's 128 points ----
    if (tid < TILE_P) {
        int p = blockIdx.x * TILE_P + tid;
        if (p >= P) p = P - 1;
        const int b = p / N;
        const int n = p - b * N;
        const float* xb = x0 + (size_t)b * 3 * N + n;
        sm[SM_X0 + tid]       = xb[0];
        sm[SM_X0 + 128 + tid] = xb[N];
        sm[SM_X0 + 256 + tid] = xb[2 * N];
    }
    __syncthreads();

    const int og = tid & 31;          // out group: outs 4*og .. 4*og+3
    const int pg = tid >> 5;          // pt group (== warp id): pts 16*pg .. 16*pg+15

    const float third = 1.0f / 3.0f;
    const float tts[4] = {0.0f, third, 2.0f * third, 1.0f};

    #pragma unroll 1
    for (int s = 0; s < 4; ++s) {
        // ---- (a) per-point RK stage input ----
        if (tid < TILE_P) {
            const int j = tid;
            #pragma unroll
            for (int c = 0; c < 3; ++c) {
                const float xv = sm[SM_X0 + c * 128 + j];
                float xin;
                if (s == 0)      xin = xv;
                else if (s == 1) xin = fmaf(sm[SM_K1 + c * 128 + j], third, xv);
                else if (s == 2) xin = xv + sm[SM_K2 + c * 128 + j]
                                        - sm[SM_K1 + c * 128 + j] * third;
                else             xin = xv + sm[SM_K1 + c * 128 + j]
                                        - sm[SM_K2 + c * 128 + j]
                                        + sm[SM_K3 + c * 128 + j];
                sm[SM_XIN + c * 128 + j] = xin;
            }
        }
        __syncthreads();

        // ---- (b) layer 1: z1[k][p] for all 128x128 elements ----
        const float tt = tts[s];
        const float4* w1h4 = (const float4*)(sm + SM_W1H);
        const float4* w1g4 = (const float4*)(sm + SM_W1G);
        #pragma unroll 4
        for (int it = 0; it < (HID * TILE_P) / THREADS; ++it) {
            const int i = tid + it * THREADS;
            const int k = i >> 7, p = i & 127;
            const float xi0 = sm[SM_XIN + p];
            const float xi1 = sm[SM_XIN + 128 + p];
            const float xi2 = sm[SM_XIN + 256 + p];
            const float4 wh = w1h4[k];
            const float4 wg = w1g4[k];
            float h = fmaf(wh.x, xi0, fmaf(wh.y, xi1,
                      fmaf(wh.z, xi2, fmaf(wh.w, tt, sm[SM_B1H + k]))));
            float g = fmaf(wg.x, xi0, fmaf(wg.y, xi1,
                      fmaf(wg.z, xi2, fmaf(wg.w, tt, sm[SM_B1G + k]))));
            sm[SM_Z + k * 128 + p] = fmaxf(h * sigmoid_f(g), 0.0f);
        }
        __syncthreads();

        // ---- (c) layer-2 GEMM: 4 outs x 16 pts x {h,g} per thread ----
        u64 acch[4][8], accg[4][8];
        #pragma unroll
        for (int oo = 0; oo < 4; ++oo)
            #pragma unroll
            for (int pp = 0; pp < 8; ++pp) { acch[oo][pp] = 0ull; accg[oo][pp] = 0ull; }

        const float4* whp = (const float4*)(sm + SM_W2HT) + og;        // +32/row
        const float4* wgp = (const float4*)(sm + SM_W2GT) + og;
        const ulonglong2* zq = (const ulonglong2*)(sm + SM_Z) + pg * 4; // +32/row

        #pragma unroll 4
        for (int k = 0; k < HID; ++k) {
            const float4 wh = whp[k * 32];
            const float4 wg = wgp[k * 32];
            ulonglong2 zv0 = zq[k * 32];
            ulonglong2 zv1 = zq[k * 32 + 1];
            ulonglong2 zv2 = zq[k * 32 + 2];
            ulonglong2 zv3 = zq[k * 32 + 3];
            u64 zp[8] = {zv0.x, zv0.y, zv1.x, zv1.y, zv2.x, zv2.y, zv3.x, zv3.y};
            const float whf[4] = {wh.x, wh.y, wh.z, wh.w};
            const float wgf[4] = {wg.x, wg.y, wg.z, wg.w};
            #pragma unroll
            for (int oo = 0; oo < 4; ++oo) {
                const u64 wdh = pack2(whf[oo], whf[oo]);
                const u64 wdg = pack2(wgf[oo], wgf[oo]);
                #pragma unroll
                for (int pp = 0; pp < 8; ++pp) {
                    acch[oo][pp] = ffma2(wdh, zp[pp], acch[oo][pp]);
                    accg[oo][pp] = ffma2(wdg, zp[pp], accg[oo][pp]);
                }
            }
        }
        __syncthreads();   // all z1 reads done; z buffer reused for z2t

        // ---- (d) gating epilogue -> z2t[pt][out] (stride Z2STR) ----
        {
            #pragma unroll
            for (int pp = 0; pp < 8; ++pp) {
                float z2a[4], z2b[4];   // two points in this pair, 4 outs each
                #pragma unroll
                for (int oo = 0; oo < 4; ++oo) {
                    const int o = 4 * og + oo;
                    float h0, h1, g0, g1;
                    unpack2(acch[oo][pp], h0, h1);
                    unpack2(accg[oo][pp], g0, g1);
                    h0 += sm[SM_B2H + o]; h1 += sm[SM_B2H + o];
                    g0 += sm[SM_B2G + o]; g1 += sm[SM_B2G + o];
                    z2a[oo] = fmaxf(h0 * sigmoid_f(g0), 0.0f);
                    z2b[oo] = fmaxf(h1 * sigmoid_f(g1), 0.0f);
                }
                const int p0 = pg * 16 + 2 * pp;
                *(float4*)(sm + SM_Z + p0 * Z2STR + 4 * og) =
                    make_float4(z2a[0], z2a[1], z2a[2], z2a[3]);
                *(float4*)(sm + SM_Z + (p0 + 1) * Z2STR + 4 * og) =
                    make_float4(z2b[0], z2b[1], z2b[2], z2b[3]);
            }
        }
        __syncthreads();

        // ---- (e) output projection + tanh + RK state update ----
        {
            const int pt   = tid >> 1;      // 0..127
            const int part = tid & 1;       // half of the 128 hidden outs
            const float4* zr = (const float4*)(sm + SM_Z + pt * Z2STR + part * 64);
            const float4* w0 = (const float4*)(sm + SM_OW + part * 64);
            const float4* w1 = (const float4*)(sm + SM_OW + 128 + part * 64);
            const float4* w2 = (const float4*)(sm + SM_OW + 256 + part * 64);
            float o0 = 0.f, o1 = 0.f, o2 = 0.f;
            #pragma unroll
            for (int i = 0; i < 16; ++i) {
                const float4 z4 = zr[i];
                const float4 a = w0[i], b4 = w1[i], c4 = w2[i];
                o0 = fmaf(a.x, z4.x, fmaf(a.y, z4.y, fmaf(a.z, z4.z, fmaf(a.w, z4.w, o0))));
                o1 = fmaf(b4.x, z4.x, fmaf(b4.y, z4.y, fmaf(b4.z, z4.z, fmaf(b4.w, z4.w, o1))));
                o2 = fmaf(c4.x, z4.x, fmaf(c4.y, z4.y, fmaf(c4.z, z4.z, fmaf(c4.w, z4.w, o2))));
            }
            o0 += __shfl_xor_sync(0xffffffffu, o0, 1);
            o1 += __shfl_xor_sync(0xffffffffu, o1, 1);
            o2 += __shfl_xor_sync(0xffffffffu, o2, 1);

            if (part == 0) {
                const float v0 = tanhf(o0 + sm[SM_OB + 0]) * 0.5f;
                const float v1 = tanhf(o1 + sm[SM_OB + 1]) * 0.5f;
                const float v2 = tanhf(o2 + sm[SM_OB + 2]) * 0.5f;
                if (s == 0) {
                    sm[SM_K1 + pt] = v0; sm[SM_K1 + 128 + pt] = v1; sm[SM_K1 + 256 + pt] = v2;
                } else if (s == 1) {
                    sm[SM_K2 + pt] = v0; sm[SM_K2 + 128 + pt] = v1; sm[SM_K2 + 256 + pt] = v2;
                } else if (s == 2) {
                    sm[SM_K3 + pt] = v0; sm[SM_K3 + 128 + pt] = v1; sm[SM_K3 + 256 + pt] = v2;
                } else {
                    const int p = blockIdx.x * TILE_P + pt;
                    if (p < P) {
                        const int b = p / N;
                        const int n = p - b * N;
                        float* op = out + (size_t)b * 3 * N + n;
                        const float k4[3] = {v0, v1, v2};
                        #pragma unroll
                        for (int c = 0; c < 3; ++c) {
                            const float r = sm[SM_X0 + c * 128 + pt] + 0.125f *
                                (sm[SM_K1 + c * 128 + pt]
                                 + 3.0f * (sm[SM_K2 + c * 128 + pt] + sm[SM_K3 + c * 128 + pt])
                                 + k4[c]);
                            op[(size_t)c * N] = r;
                        }
                    }
                }
            }
        }
        __syncthreads();
    }
}

extern "C" void kernel_launch(void* const* d_in, const int* in_sizes, int n_in,
                              void* d_out, int out_size)
{
    const float* x0  = (const float*)d_in[0];
    const float* h1w = (const float*)d_in[1];
    const float* h1b = (const float*)d_in[2];
    const float* g1w = (const float*)d_in[3];
    const float* g1b = (const float*)d_in[4];
    const float* h2w = (const float*)d_in[5];
    const float* h2b = (const float*)d_in[6];
    const float* g2w = (const float*)d_in[7];
    const float* g2b = (const float*)d_in[8];
    const float* ow  = (const float*)d_in[9];
    const float* ob  = (const float*)d_in[10];
    float* out = (float*)d_out;

    const int N = NP;
    const int B = in_sizes[0] / (3 * N);
    const int P = B * N;

    cudaFuncSetAttribute(node_rk4_kernel,
                         cudaFuncAttributeMaxDynamicSharedMemorySize, SM_BYTES);

    const int blocks = (P + TILE_P - 1) / TILE_P;
    node_rk4_kernel<<<blocks, THREADS, SM_BYTES>>>(
        x0, h1w, h1b, g1w, g1b, h2w, h2b, g2w, g2b, ow, ob, out, B, N);
}

// round 11
// speedup vs baseline: 9.4747x; 3.3065x over previous
#include <cuda_runtime.h>
#include <cuda_fp16.h>
#include <cstdint>

#define THREADS 256
#define TILE_P 128
#define NP 50000
#define HID 128
#define Z2STR 132
#define KPAD 136                   // halfs per row (272B, 16B-aligned, bank-staggered)

// ---- dynamic smem byte layout ----
#define SB_AH 0                            // W2h fp16 [out][KPAD]  34816B
#define SB_AG (SB_AH + HID * KPAD * 2)     // W2g fp16
#define SB_B  (SB_AG + HID * KPAD * 2)     // z1 fp16 [pt][KPAD]
#define SB_Z2 (SB_B + HID * KPAD * 2)      // z2t fp32 [128][Z2STR]
#define SB_F  (SB_Z2 + 128 * Z2STR * 4)
// float offsets within SB_F
#define F_W1H 0
#define F_W1G 512
#define F_B1H 1024
#define F_B1G 1152
#define F_B2H 1280
#define F_B2G 1408
#define F_OW  1536
#define F_OB  1920
#define F_X0  1924
#define F_K1  2308
#define F_K2  2692
#define F_K3  3076
#define F_XIN 3460
#define F_TOT 3844
#define SM_BYTES (SB_F + F_TOT * 4)

__device__ __forceinline__ uint32_t smem_u32(const void* p) {
    uint32_t a;
    asm("{ .reg .u64 t; cvta.to.shared.u64 t, %1; cvt.u32.u64 %0, t; }" : "=r"(a) : "l"(p));
    return a;
}
__device__ __forceinline__ float sigmoid_f(float x) {
    return __fdividef(1.0f, 1.0f + __expf(-x));
}
__device__ __forceinline__ void ldsm_x4(uint32_t* r, uint32_t addr) {
    asm volatile("ldmatrix.sync.aligned.m8n8.x4.shared.b16 {%0,%1,%2,%3}, [%4];"
                 : "=r"(r[0]), "=r"(r[1]), "=r"(r[2]), "=r"(r[3]) : "r"(addr));
}
__device__ __forceinline__ void mma16816(float* d, const uint32_t* a,
                                         uint32_t b0, uint32_t b1) {
    asm volatile("mma.sync.aligned.m16n8k16.row.col.f32.f16.f16.f32 "
                 "{%0,%1,%2,%3}, {%4,%5,%6,%7}, {%8,%9}, {%0,%1,%2,%3};"
                 : "+f"(d[0]), "+f"(d[1]), "+f"(d[2]), "+f"(d[3])
                 : "r"(a[0]), "r"(a[1]), "r"(a[2]), "r"(a[3]), "r"(b0), "r"(b1));
}

__global__ void __launch_bounds__(THREADS, 1)
node_rk4_kernel(const float* __restrict__ x0,
                const float* __restrict__ h1w, const float* __restrict__ h1b,
                const float* __restrict__ g1w, const float* __restrict__ g1b,
                const float* __restrict__ h2w, const float* __restrict__ h2b,
                const float* __restrict__ g2w, const float* __restrict__ g2b,
                const float* __restrict__ ow,  const float* __restrict__ ob,
                float* __restrict__ out, int B, int N)
{
    extern __shared__ char smem[];
    float* sf = (float*)(smem + SB_F);
    const uint32_t smb = smem_u32(smem);
    const int tid = threadIdx.x;
    const int wid = tid >> 5, lid = tid & 31;
    const int P = B * N;

    // ---- stage layer-2 weights -> fp16 [out][KPAD] k-major ----
    for (int i = tid * 2; i < HID * HID; i += THREADS * 2) {
        const int o = i >> 7, k = i & 127;
        const float2 vh = *(const float2*)(h2w + i);
        const float2 vg = *(const float2*)(g2w + i);
        const uint32_t off = (uint32_t)(o * KPAD + k) * 2;
        *(__half2*)(smem + SB_AH + off) = __floats2half2_rn(vh.x, vh.y);
        *(__half2*)(smem + SB_AG + off) = __floats2half2_rn(vg.x, vg.y);
    }
    // ---- small params ----
    for (int i = tid; i < HID * 4; i += THREADS) {
        sf[F_W1H + i] = h1w[i];
        sf[F_W1G + i] = g1w[i];
    }
    if (tid < HID) {
        sf[F_B1H + tid] = h1b[tid];
        sf[F_B1G + tid] = g1b[tid];
        sf[F_B2H + tid] = h2b[tid];
        sf[F_B2G + tid] = g2b[tid];
    }
    for (int i = tid; i < 3 * HID; i += THREADS) sf[F_OW + i] = ow[i];
    if (tid < 3) sf[F_OB + tid] = ob[tid];

    // ---- stage x0 for this CTA's 128 points ----
    if (tid < TILE_P) {
        int p = blockIdx.x * TILE_P + tid;
        if (p >= P) p = P - 1;
        const int b = p / N;
        const int n = p - b * N;
        const float* xb = x0 + (size_t)b * 3 * N + n;
        sf[F_X0 + tid]       = xb[0];
        sf[F_X0 + 128 + tid] = xb[N];
        sf[F_X0 + 256 + tid] = xb[2 * N];
    }
    __syncthreads();

    // ---- warp GEMM geometry (8 warps, 32-out x 64-pt quadrant, both gates) ----
    const int obk = wid & 3;                 // out block: 32*obk
    const int pbk = wid >> 2;                // pt block: 64*pbk
    const int rA = lid & 15;
    const int cA = (lid >> 4) << 3;          // 0 or 8 (halfs)
    const uint32_t a_h0 = smb + SB_AH + (uint32_t)((obk * 32 + rA) * KPAD + cA) * 2;
    const uint32_t a_h1 = a_h0 + 16 * KPAD * 2;
    const uint32_t a_g0 = a_h0 + (SB_AG - SB_AH);
    const uint32_t a_g1 = a_h1 + (SB_AG - SB_AH);
    uint32_t b_q[4];
    #pragma unroll
    for (int q = 0; q < 4; ++q)
        b_q[q] = smb + SB_B + (uint32_t)((pbk * 64 + q * 16 + rA) * KPAD + cA) * 2;

    const float third = 1.0f / 3.0f;
    const float tts[4] = {0.0f, third, 2.0f * third, 1.0f};

    #pragma unroll 1
    for (int s = 0; s < 4; ++s) {
        // ---- (a) RK stage input ----
        if (tid < TILE_P) {
            const int j = tid;
            #pragma unroll
            for (int c = 0; c < 3; ++c) {
                const float xv = sf[F_X0 + c * 128 + j];
                float xin;
                if (s == 0)      xin = xv;
                else if (s == 1) xin = fmaf(sf[F_K1 + c * 128 + j], third, xv);
                else if (s == 2) xin = xv + sf[F_K2 + c * 128 + j]
                                        - sf[F_K1 + c * 128 + j] * third;
                else             xin = xv + sf[F_K1 + c * 128 + j]
                                        - sf[F_K2 + c * 128 + j]
                                        + sf[F_K3 + c * 128 + j];
                sf[F_XIN + c * 128 + j] = xin;
            }
        }
        __syncthreads();

        // ---- (b) layer 1 -> z1 fp16 [pt][KPAD] ----
        {
            const float tt = tts[s];
            const int pt = tid & 127;
            const int kb = (tid >> 7) * 64;          // 0 or 64
            const float xi0 = sf[F_XIN + pt];
            const float xi1 = sf[F_XIN + 128 + pt];
            const float xi2 = sf[F_XIN + 256 + pt];
            const float4* w1h4 = (const float4*)(sf + F_W1H);
            const float4* w1g4 = (const float4*)(sf + F_W1G);
            #pragma unroll 4
            for (int kk = 0; kk < 64; kk += 2) {
                const int k = kb + kk;
                float zz[2];
                #pragma unroll
                for (int u = 0; u < 2; ++u) {
                    const float4 wh = w1h4[k + u];
                    const float4 wg = w1g4[k + u];
                    const float h = fmaf(wh.x, xi0, fmaf(wh.y, xi1,
                                    fmaf(wh.z, xi2, fmaf(wh.w, tt, sf[F_B1H + k + u]))));
                    const float g = fmaf(wg.x, xi0, fmaf(wg.y, xi1,
                                    fmaf(wg.z, xi2, fmaf(wg.w, tt, sf[F_B1G + k + u]))));
                    zz[u] = fmaxf(h * sigmoid_f(g), 0.0f);
                }
                *(__half2*)(smem + SB_B + (uint32_t)(pt * KPAD + k) * 2) =
                    __floats2half2_rn(zz[0], zz[1]);
            }
        }
        __syncthreads();

        // ---- (c) layer-2 GEMM via HMMA (mma.sync m16n8k16) ----
        float acc_h[2][8][4], acc_g[2][8][4];
        #pragma unroll
        for (int mt = 0; mt < 2; ++mt)
            #pragma unroll
            for (int nt = 0; nt < 8; ++nt)
                #pragma unroll
                for (int c = 0; c < 4; ++c) { acc_h[mt][nt][c] = 0.f; acc_g[mt][nt][c] = 0.f; }

        #pragma unroll
        for (int ks = 0; ks < 8; ++ks) {
            const uint32_t ko = (uint32_t)ks * 32;   // 16 halfs
            uint32_t Ah[2][4], Ag[2][4], Bq[4][4];
            ldsm_x4(Ah[0], a_h0 + ko);
            ldsm_x4(Ah[1], a_h1 + ko);
            ldsm_x4(Ag[0], a_g0 + ko);
            ldsm_x4(Ag[1], a_g1 + ko);
            #pragma unroll
            for (int q = 0; q < 4; ++q) ldsm_x4(Bq[q], b_q[q] + ko);
            #pragma unroll
            for (int mt = 0; mt < 2; ++mt) {
                #pragma unroll
                for (int nt = 0; nt < 8; ++nt) {
                    const int q = nt >> 1;
                    const uint32_t b0 = (nt & 1) ? Bq[q][1] : Bq[q][0];
                    const uint32_t b1 = (nt & 1) ? Bq[q][3] : Bq[q][2];
                    mma16816(acc_h[mt][nt], Ah[mt], b0, b1);
                    mma16816(acc_g[mt][nt], Ag[mt], b0, b1);
                }
            }
        }

        // ---- (d) gating epilogue in registers -> z2t[pt][out] ----
        {
            const int gid = lid >> 2, tig = lid & 3;
            float* z2t = (float*)(smem + SB_Z2);
            #pragma unroll
            for (int mt = 0; mt < 2; ++mt) {
                const int o0 = obk * 32 + mt * 16 + gid;
                const int o8 = o0 + 8;
                const float bh0 = sf[F_B2H + o0], bh8 = sf[F_B2H + o8];
                const float bg0 = sf[F_B2G + o0], bg8 = sf[F_B2G + o8];
                #pragma unroll
                for (int nt = 0; nt < 8; ++nt) {
                    const int p0 = pbk * 64 + nt * 8 + 2 * tig;
                    const float* ah = acc_h[mt][nt];
                    const float* ag = acc_g[mt][nt];
                    z2t[p0 * Z2STR + o0] =
                        fmaxf((ah[0] + bh0) * sigmoid_f(ag[0] + bg0), 0.f);
                    z2t[(p0 + 1) * Z2STR + o0] =
                        fmaxf((ah[1] + bh0) * sigmoid_f(ag[1] + bg0), 0.f);
                    z2t[p0 * Z2STR + o8] =
                        fmaxf((ah[2] + bh8) * sigmoid_f(ag[2] + bg8), 0.f);
                    z2t[(p0 + 1) * Z2STR + o8] =
                        fmaxf((ah[3] + bh8) * sigmoid_f(ag[3] + bg8), 0.f);
                }
            }
        }
        __syncthreads();

        // ---- (e) output projection + tanh + RK state update ----
        {
            const int pt   = tid >> 1;
            const int part = tid & 1;
            const float* z2t = (const float*)(smem + SB_Z2);
            const float4* zr = (const float4*)(z2t + pt * Z2STR + part * 64);
            const float4* w0 = (const float4*)(sf + F_OW + part * 64);
            const float4* w1 = (const float4*)(sf + F_OW + 128 + part * 64);
            const float4* w2 = (const float4*)(sf + F_OW + 256 + part * 64);
            float o0 = 0.f, o1 = 0.f, o2 = 0.f;
            #pragma unroll
            for (int i = 0; i < 16; ++i) {
                const float4 z4 = zr[i];
                const float4 a = w0[i], b4 = w1[i], c4 = w2[i];
                o0 = fmaf(a.x, z4.x, fmaf(a.y, z4.y, fmaf(a.z, z4.z, fmaf(a.w, z4.w, o0))));
                o1 = fmaf(b4.x, z4.x, fmaf(b4.y, z4.y, fmaf(b4.z, z4.z, fmaf(b4.w, z4.w, o1))));
                o2 = fmaf(c4.x, z4.x, fmaf(c4.y, z4.y, fmaf(c4.z, z4.z, fmaf(c4.w, z4.w, o2))));
            }
            o0 += __shfl_xor_sync(0xffffffffu, o0, 1);
            o1 += __shfl_xor_sync(0xffffffffu, o1, 1);
            o2 += __shfl_xor_sync(0xffffffffu, o2, 1);

            if (part == 0) {
                const float v0 = tanhf(o0 + sf[F_OB + 0]) * 0.5f;
                const float v1 = tanhf(o1 + sf[F_OB + 1]) * 0.5f;
                const float v2 = tanhf(o2 + sf[F_OB + 2]) * 0.5f;
                if (s == 0) {
                    sf[F_K1 + pt] = v0; sf[F_K1 + 128 + pt] = v1; sf[F_K1 + 256 + pt] = v2;
                } else if (s == 1) {
                    sf[F_K2 + pt] = v0; sf[F_K2 + 128 + pt] = v1; sf[F_K2 + 256 + pt] = v2;
                } else if (s == 2) {
                    sf[F_K3 + pt] = v0; sf[F_K3 + 128 + pt] = v1; sf[F_K3 + 256 + pt] = v2;
                } else {
                    const int p = blockIdx.x * TILE_P + pt;
                    if (p < P) {
                        const int b = p / N;
                        const int n = p - b * N;
                        float* op = out + (size_t)b * 3 * N + n;
                        const float k4[3] = {v0, v1, v2};
                        #pragma unroll
                        for (int c = 0; c < 3; ++c) {
                            const float r = sf[F_X0 + c * 128 + pt] + 0.125f *
                                (sf[F_K1 + c * 128 + pt]
                                 + 3.0f * (sf[F_K2 + c * 128 + pt] + sf[F_K3 + c * 128 + pt])
                                 + k4[c]);
                            op[(size_t)c * N] = r;
                        }
                    }
                }
            }
        }
        __syncthreads();
    }
}

extern "C" void kernel_launch(void* const* d_in, const int* in_sizes, int n_in,
                              void* d_out, int out_size)
{
    const float* x0  = (const float*)d_in[0];
    const float* h1w = (const float*)d_in[1];
    const float* h1b = (const float*)d_in[2];
    const float* g1w = (const float*)d_in[3];
    const float* g1b = (const float*)d_in[4];
    const float* h2w = (const float*)d_in[5];
    const float* h2b = (const float*)d_in[6];
    const float* g2w = (const float*)d_in[7];
    const float* g2b = (const float*)d_in[8];
    const float* ow  = (const float*)d_in[9];
    const float* ob  = (const float*)d_in[10];
    float* out = (float*)d_out;

    const int N = NP;
    const int B = in_sizes[0] / (3 * N);
    const int P = B * N;

    cudaFuncSetAttribute(node_rk4_kernel,
                         cudaFuncAttributeMaxDynamicSharedMemorySize, SM_BYTES);

    const int blocks = (P + TILE_P - 1) / TILE_P;
    node_rk4_kernel<<<blocks, THREADS, SM_BYTES>>>(
        x0, h1w, h1b, g1w, g1b, h2w, h2b, g2w, g2b, ow, ob, out, B, N);
}